// round 15
// baseline (speedup 1.0000x reference)
#include <cuda_runtime.h>
#include <cuda_fp16.h>
#include <math.h>
#include <stdint.h>

#define S_LEN 1024
#define NHEADS 128
#define DQd 192
#define DNd 128
#define DVd 128
#define DMODEL 7168
#define QLORA 1536
#define KVLORA 512
#define EQ (NHEADS * DQd)   // 24576
#define EV (NHEADS * DVd)   // 16384

// ---- scratch (__device__ globals; allocation-free rule) ----
__device__ __half g_xh[(size_t)S_LEN * DMODEL];
__device__ __half g_wqah[(size_t)QLORA * DMODEL];
__device__ __half g_wkvah[(size_t)KVLORA * DMODEL];
__device__ __half g_wqbh[(size_t)EQ * QLORA];
__device__ __half g_wkbh[(size_t)EQ * KVLORA];
__device__ __half g_wvbh[(size_t)EV * KVLORA];
__device__ __half g_woh[(size_t)DMODEL * EV];
__device__ float  g_qlp[(size_t)8 * S_LEN * QLORA];
__device__ float  g_kvlp[(size_t)8 * S_LEN * KVLORA];
__device__ float  g_outp[(size_t)4 * S_LEN * DMODEL];
__device__ __half g_qlath[(size_t)S_LEN * QLORA];
__device__ __half g_kvlath[(size_t)S_LEN * KVLORA];
__device__ __half g_qh[(size_t)S_LEN * EQ];
__device__ __half g_kh[(size_t)S_LEN * EQ];
__device__ __half g_vth[(size_t)EV * S_LEN];        // V^T per head: [h*128+d][s]
__device__ __half g_aoh[(size_t)S_LEN * EV];

__device__ __forceinline__ void cp_async16(uint32_t dst, const void* src) {
    asm volatile("cp.async.cg.shared.global [%0], [%1], 16;\n" :: "r"(dst), "l"(src));
}
#define CP_COMMIT() asm volatile("cp.async.commit_group;\n" ::: "memory")
#define CP_WAIT0()  asm volatile("cp.async.wait_group 0;\n" ::: "memory")
#define CP_WAIT1()  asm volatile("cp.async.wait_group 1;\n" ::: "memory")

__device__ __forceinline__ void ldsm_x4(unsigned* r, uint32_t addr) {
    asm volatile("ldmatrix.sync.aligned.m8n8.x4.shared.b16 {%0,%1,%2,%3}, [%4];"
                 : "=r"(r[0]), "=r"(r[1]), "=r"(r[2]), "=r"(r[3]) : "r"(addr));
}
__device__ __forceinline__ void mma_f16(float* d, const unsigned* a, unsigned b0, unsigned b1) {
    asm volatile(
        "mma.sync.aligned.m16n8k16.row.col.f32.f16.f16.f32 "
        "{%0,%1,%2,%3}, {%4,%5,%6,%7}, {%8,%9}, {%0,%1,%2,%3};"
        : "+f"(d[0]), "+f"(d[1]), "+f"(d[2]), "+f"(d[3])
        : "r"(a[0]), "r"(a[1]), "r"(a[2]), "r"(a[3]), "r"(b0), "r"(b1));
}
__device__ __forceinline__ unsigned ph2(float a, float b) {
    __half2 h = __floats2half2_rn(a, b);
    return *(unsigned*)&h;
}

// ---------------------------------------------------------------------------
// C[M,N] = A[M,K] @ B^T (B is [N,K] row-major), fp16 in, fp32 accumulate.
// Block 128x128, kTile 64 halves, 8 warps of 32x64 (m16n8k16 + ldmatrix).
// 3-stage cp.async pipeline (32KB/stage, 96KB total), 2 CTAs/SM.
// M,N % 128 == 0, K % 64 == 0. XOR swizzle: phys16Bchunk = logical ^ (row&7).
// OUT: 0 = fp32 C, 1 = fp16 C.
// SWAP: m0 from blockIdx.x (fast axis) — adjacent CTAs share the B tile.
// kChunk>0: split-K (z = k-window, C plane z*sC); else z = batch via sA/sB/sC.
// ---------------------------------------------------------------------------
#define KT 64
#define STG_B 32768   // bytes per stage (A 16KB + B 16KB)

template <int OUT, bool SWAP>
__global__ __launch_bounds__(256, 2) void hgemm_nt(
    const __half* __restrict__ Ag, const __half* __restrict__ Bg, void* __restrict__ Cg,
    int K, int lda, int ldb, int ldc, long sA, long sB, long sC, int kChunk)
{
    extern __shared__ char smraw[];
    const uint32_t smb = (uint32_t)__cvta_generic_to_shared(smraw);

    const int z = blockIdx.z;
    const __half *A, *B;
    int Keff;
    if (kChunk) { A = Ag + (long)z * kChunk; B = Bg + (long)z * kChunk; Keff = kChunk; }
    else        { A = Ag + (long)z * sA;     B = Bg + (long)z * sB;     Keff = K; }
    float*  Cf = (float*)Cg  + (long)z * sC;
    __half* Ch = (__half*)Cg + (long)z * sC;

    const int m0 = (SWAP ? blockIdx.x : blockIdx.y) * 128;
    const int n0 = (SWAP ? blockIdx.y : blockIdx.x) * 128;
    const int t = threadIdx.x, w = t >> 5, lane = t & 31;
    const int wm = w >> 1, wn = w & 1;

    const int srow = t >> 1, c0 = (t & 1) * 4;
    const int rx = srow & 7;
    const __half* Asrc = A + (long)(m0 + srow) * lda + c0 * 8;
    const __half* Bsrc = B + (long)(n0 + srow) * ldb + c0 * 8;
    const uint32_t sAr = smb + srow * 128;
    const uint32_t sBr = smb + 16384 + srow * 128;

    float acc[2][8][4] = {};
    const int niter = Keff / KT;

#pragma unroll
    for (int i = 0; i < 4; ++i) {
        cp_async16(sAr + (((c0 + i) ^ rx) << 4), Asrc + i * 8);
        cp_async16(sBr + (((c0 + i) ^ rx) << 4), Bsrc + i * 8);
    }
    CP_COMMIT();
    if (niter > 1) {
#pragma unroll
        for (int i = 0; i < 4; ++i) {
            cp_async16(sAr + STG_B + (((c0 + i) ^ rx) << 4), Asrc + KT + i * 8);
            cp_async16(sBr + STG_B + (((c0 + i) ^ rx) << 4), Bsrc + KT + i * 8);
        }
        CP_COMMIT();
    }

    const int a_r = (lane & 7) + ((lane >> 3) & 1) * 8;
    const int a_c = lane >> 4;
    const int b_r = (lane & 7) + ((lane >> 4) & 1) * 8;
    const int b_c = (lane >> 3) & 1;

    int stage = 0;
    for (int it = 0; it < niter; ++it) {
        if (it + 1 < niter) { CP_WAIT1(); } else { CP_WAIT0(); }
        __syncthreads();

        if (it + 2 < niter) {
            int ns = stage + 2; if (ns >= 3) ns -= 3;
            const uint32_t off = ns * STG_B;
            const int k0 = (it + 2) * KT;
#pragma unroll
            for (int i = 0; i < 4; ++i) {
                cp_async16(sAr + off + (((c0 + i) ^ rx) << 4), Asrc + k0 + i * 8);
                cp_async16(sBr + off + (((c0 + i) ^ rx) << 4), Bsrc + k0 + i * 8);
            }
            CP_COMMIT();
        }

        const uint32_t saA = smb + stage * STG_B;
        const uint32_t saB = saA + 16384;

#pragma unroll
        for (int kc = 0; kc < 4; ++kc) {
            unsigned af[2][4];
#pragma unroll
            for (int mt = 0; mt < 2; ++mt) {
                const int r = wm * 32 + mt * 16 + a_r;
                ldsm_x4(af[mt], saA + r * 128 + (((kc * 2 + a_c) ^ (r & 7)) << 4));
            }
#pragma unroll
            for (int ntt = 0; ntt < 4; ++ntt) {
                const int r = wn * 64 + ntt * 16 + b_r;
                unsigned bf[4];
                ldsm_x4(bf, saB + r * 128 + (((kc * 2 + b_c) ^ (r & 7)) << 4));
#pragma unroll
                for (int mt = 0; mt < 2; ++mt) {
                    mma_f16(acc[mt][2 * ntt],     af[mt], bf[0], bf[1]);
                    mma_f16(acc[mt][2 * ntt + 1], af[mt], bf[2], bf[3]);
                }
            }
        }
        ++stage; if (stage == 3) stage = 0;
    }

    const int g = lane >> 2, tq = lane & 3;
#pragma unroll
    for (int mt = 0; mt < 2; ++mt) {
        const int rr = m0 + wm * 32 + mt * 16 + g;
#pragma unroll
        for (int nt = 0; nt < 8; ++nt) {
            const int cc = n0 + wn * 64 + nt * 8 + tq * 2;
            if (OUT == 0) {
                *(float2*)(Cf + (long)rr * ldc + cc) =
                    make_float2(acc[mt][nt][0], acc[mt][nt][1]);
                *(float2*)(Cf + (long)(rr + 8) * ldc + cc) =
                    make_float2(acc[mt][nt][2], acc[mt][nt][3]);
            } else {
                *(__half2*)(Ch + (long)rr * ldc + cc) =
                    __floats2half2_rn(acc[mt][nt][0], acc[mt][nt][1]);
                *(__half2*)(Ch + (long)(rr + 8) * ldc + cc) =
                    __floats2half2_rn(acc[mt][nt][2], acc[mt][nt][3]);
            }
        }
    }
}

// ---------------------------------------------------------------------------
// Fused flash attention (unchanged, passing since R13).
// ---------------------------------------------------------------------------
#define FA_KSTG 49152
#define FA_VSTG 32768
#define FA_SMEM (FA_KSTG * 3 + FA_VSTG * 2)   // 212992

__global__ __launch_bounds__(256, 1) void flash_attn(
    const __half* __restrict__ Qg,   // [S][H][192]
    const __half* __restrict__ Kg,   // [S][H][192]
    const __half* __restrict__ Vt,   // [H*128][S]
    __half* __restrict__ Og)         // [S][H*128]
{
    extern __shared__ char smraw[];
    const uint32_t smb = (uint32_t)__cvta_generic_to_shared(smraw);
    const uint32_t Qs  = smb;
    const uint32_t Ks0 = smb + FA_KSTG;
    const uint32_t Vs0 = smb + FA_KSTG * 3;

    const int qb = blockIdx.x * 128;
    const int h  = blockIdx.y;
    const int t = threadIdx.x, w = t >> 5, lane = t & 31;
    const int g = lane >> 2, tq = lane & 3;

    const int srow = t >> 1, rx = srow & 7;
    const int cbase = (t & 1) * 12;
    const int vcbase = (t & 1) * 8;
    const __half* Qsrc = Qg + ((long)(qb + srow) * NHEADS + h) * DQd;
    const __half* Ksrc = Kg + ((long)srow * NHEADS + h) * DQd;
    const __half* Vsrc = Vt + (long)(h * 128 + srow) * S_LEN;
    const long KBLK = (long)128 * NHEADS * DQd;

#pragma unroll
    for (int i = 0; i < 12; ++i) {
        const int c = cbase + i;
        cp_async16(Qs  + srow * 384 + ((c ^ rx) << 4), Qsrc + c * 8);
        cp_async16(Ks0 + srow * 384 + ((c ^ rx) << 4), Ksrc + c * 8);
    }
#pragma unroll
    for (int i = 0; i < 8; ++i) {
        const int c = vcbase + i;
        cp_async16(Vs0 + srow * 256 + ((c ^ rx) << 4), Vsrc + c * 8);
    }
    CP_COMMIT();
#pragma unroll
    for (int i = 0; i < 12; ++i) {
        const int c = cbase + i;
        cp_async16(Ks0 + FA_KSTG + srow * 384 + ((c ^ rx) << 4), Ksrc + KBLK + c * 8);
    }
#pragma unroll
    for (int i = 0; i < 8; ++i) {
        const int c = vcbase + i;
        cp_async16(Vs0 + FA_VSTG + srow * 256 + ((c ^ rx) << 4), Vsrc + 128 + c * 8);
    }
    CP_COMMIT();

    const int a_r = (lane & 7) + ((lane >> 3) & 1) * 8;
    const int a_c = lane >> 4;
    const int b_r = (lane & 7) + ((lane >> 4) & 1) * 8;
    const int b_c = (lane >> 3) & 1;

    float oacc[16][4] = {};
    float m0 = -1e30f, m1 = -1e30f, l0 = 0.f, l1 = 0.f;
    const float ksc = 0.07216878364870323f * 1.4426950408889634f;

    for (int kb = 0; kb < 8; ++kb) {
        if (kb < 7) { CP_WAIT1(); } else { CP_WAIT0(); }
        __syncthreads();
        const uint32_t Kst = Ks0 + (kb & 1) * FA_KSTG;
        const uint32_t Vst = Vs0 + (kb & 1) * FA_VSTG;

        float sacc[16][4] = {};
#pragma unroll
        for (int kc = 0; kc < 12; ++kc) {
            unsigned aq[4];
            {
                const int r = w * 16 + a_r;
                ldsm_x4(aq, Qs + r * 384 + (((kc * 2 + a_c) ^ (r & 7)) << 4));
            }
#pragma unroll
            for (int ntt = 0; ntt < 8; ++ntt) {
                const int r = ntt * 16 + b_r;
                unsigned bk[4];
                ldsm_x4(bk, Kst + r * 384 + (((kc * 2 + b_c) ^ (r & 7)) << 4));
                mma_f16(sacc[2 * ntt],     aq, bk[0], bk[1]);
                mma_f16(sacc[2 * ntt + 1], aq, bk[2], bk[3]);
            }
        }

        float bm0 = -1e30f, bm1 = -1e30f;
#pragma unroll
        for (int nt = 0; nt < 16; ++nt) {
            bm0 = fmaxf(bm0, fmaxf(sacc[nt][0], sacc[nt][1]));
            bm1 = fmaxf(bm1, fmaxf(sacc[nt][2], sacc[nt][3]));
        }
        bm0 = fmaxf(bm0, __shfl_xor_sync(0xffffffffu, bm0, 1));
        bm0 = fmaxf(bm0, __shfl_xor_sync(0xffffffffu, bm0, 2));
        bm1 = fmaxf(bm1, __shfl_xor_sync(0xffffffffu, bm1, 1));
        bm1 = fmaxf(bm1, __shfl_xor_sync(0xffffffffu, bm1, 2));
        const float mn0 = fmaxf(m0, bm0), mn1 = fmaxf(m1, bm1);
        const float al0 = exp2f(ksc * (m0 - mn0));
        const float al1 = exp2f(ksc * (m1 - mn1));
        l0 *= al0; l1 *= al1;
#pragma unroll
        for (int nt = 0; nt < 16; ++nt) {
            oacc[nt][0] *= al0; oacc[nt][1] *= al0;
            oacc[nt][2] *= al1; oacc[nt][3] *= al1;
        }
        m0 = mn0; m1 = mn1;

        unsigned pa[8][4];
        float s0 = 0.f, s1 = 0.f;
#pragma unroll
        for (int j = 0; j < 8; ++j) {
            const float p00 = exp2f(ksc * (sacc[2*j][0] - mn0));
            const float p01 = exp2f(ksc * (sacc[2*j][1] - mn0));
            const float p02 = exp2f(ksc * (sacc[2*j][2] - mn1));
            const float p03 = exp2f(ksc * (sacc[2*j][3] - mn1));
            const float p10 = exp2f(ksc * (sacc[2*j+1][0] - mn0));
            const float p11 = exp2f(ksc * (sacc[2*j+1][1] - mn0));
            const float p12 = exp2f(ksc * (sacc[2*j+1][2] - mn1));
            const float p13 = exp2f(ksc * (sacc[2*j+1][3] - mn1));
            s0 += p00 + p01 + p10 + p11;
            s1 += p02 + p03 + p12 + p13;
            pa[j][0] = ph2(p00, p01);
            pa[j][1] = ph2(p02, p03);
            pa[j][2] = ph2(p10, p11);
            pa[j][3] = ph2(p12, p13);
        }
        s0 += __shfl_xor_sync(0xffffffffu, s0, 1);
        s0 += __shfl_xor_sync(0xffffffffu, s0, 2);
        s1 += __shfl_xor_sync(0xffffffffu, s1, 1);
        s1 += __shfl_xor_sync(0xffffffffu, s1, 2);
        l0 += s0; l1 += s1;

#pragma unroll
        for (int j = 0; j < 8; ++j) {
#pragma unroll
            for (int nt2 = 0; nt2 < 8; ++nt2) {
                const int r = nt2 * 16 + b_r;
                unsigned bv[4];
                ldsm_x4(bv, Vst + r * 256 + (((j * 2 + b_c) ^ (r & 7)) << 4));
                mma_f16(oacc[2 * nt2],     pa[j], bv[0], bv[1]);
                mma_f16(oacc[2 * nt2 + 1], pa[j], bv[2], bv[3]);
            }
        }

        __syncthreads();
        if (kb + 2 < 8) {
            const long koff = (long)(kb + 2) * 128;
            const uint32_t Kd = Ks0 + (kb & 1) * FA_KSTG;
            const uint32_t Vd = Vs0 + (kb & 1) * FA_VSTG;
#pragma unroll
            for (int i = 0; i < 12; ++i) {
                const int c = cbase + i;
                cp_async16(Kd + srow * 384 + ((c ^ rx) << 4),
                           Ksrc + koff * NHEADS * DQd + c * 8);
            }
#pragma unroll
            for (int i = 0; i < 8; ++i) {
                const int c = vcbase + i;
                cp_async16(Vd + srow * 256 + ((c ^ rx) << 4), Vsrc + koff + c * 8);
            }
            CP_COMMIT();
        }
    }

    const float i0 = 1.f / l0, i1 = 1.f / l1;
    const int r0 = qb + w * 16 + g;
    __half* orow0 = Og + (long)r0 * EV + h * 128;
    __half* orow1 = orow0 + (long)8 * EV;
#pragma unroll
    for (int nt = 0; nt < 16; ++nt) {
        *(__half2*)(orow0 + nt * 8 + tq * 2) =
            __floats2half2_rn(oacc[nt][0] * i0, oacc[nt][1] * i0);
        *(__half2*)(orow1 + nt * 8 + tq * 2) =
            __floats2half2_rn(oacc[nt][2] * i1, oacc[nt][3] * i1);
    }
}

// ---- fused fp32 -> fp16 conversion of all 7 inputs (ONE launch) ----
struct CvtPtrs { const float* s[7]; __half* d[7]; };
__global__ void cvt_all(CvtPtrs p)
{
    const long seg[7] = {1835008, 2752512, 917504, 9437184, 3145728, 2097152, 29360128};
    long i = (long)blockIdx.x * blockDim.x + threadIdx.x;
    long rem = i;
    int j = 0;
#pragma unroll
    for (int k = 0; k < 7; ++k) {
        if (j == k && rem >= seg[k]) { rem -= seg[k]; j = k + 1; }
    }
    if (j >= 7) return;
    float4 v = ((const float4*)p.s[j])[rem];
    __half2* dst = (__half2*)p.d[j] + rem * 2;
    dst[0] = __floats2half2_rn(v.x, v.y);
    dst[1] = __floats2half2_rn(v.z, v.w);
}

// Split-K reduce: fp32 partials -> fp16 output
template <int P>
__global__ void reduce_kh(const float* __restrict__ in, __half* __restrict__ out,
                          int n4, long stride4)
{
    int i = blockIdx.x * blockDim.x + threadIdx.x;
    if (i >= n4) return;
    float4 s = ((const float4*)in)[i];
#pragma unroll
    for (int p = 1; p < P; ++p) {
        float4 v = ((const float4*)in)[i + (long)p * stride4];
        s.x += v.x; s.y += v.y; s.z += v.z; s.w += v.w;
    }
    __half2* d = (__half2*)out + i * 2;
    d[0] = __floats2half2_rn(s.x, s.y);
    d[1] = __floats2half2_rn(s.z, s.w);
}

// Split-K reduce: fp32 partials -> fp32 output
template <int P>
__global__ void reduce_kf(const float* __restrict__ in, float* __restrict__ out,
                          int n4, long stride4)
{
    int i = blockIdx.x * blockDim.x + threadIdx.x;
    if (i >= n4) return;
    float4 s = ((const float4*)in)[i];
#pragma unroll
    for (int p = 1; p < P; ++p) {
        float4 v = ((const float4*)in)[i + (long)p * stride4];
        s.x += v.x; s.y += v.y; s.z += v.z; s.w += v.w;
    }
    ((float4*)out)[i] = s;
}

// Fused interleaved RoPE over dims [128,192) for BOTH q and k.
__global__ void rope_qk(__half* __restrict__ Q, __half* __restrict__ K)
{
    long idx = (long)blockIdx.x * blockDim.x + threadIdx.x;
    if (idx >= (long)2 * S_LEN * NHEADS * 32) return;
    __half* X = (idx >> 22) ? K : Q;
    long id = idx & 0x3FFFFF;
    int i = (int)(id & 31);
    int h = (int)((id >> 5) & (NHEADS - 1));
    int s = (int)(id >> 12);

    int m = (2 * i) & 31;
    float invf = (float)pow(10000.0, -(double)m / 32.0);
    float ang = (float)s * invf;
    float sn, cs;
    sincosf(ang, &sn, &cs);

    __half2* p = (__half2*)(X + ((long)s * NHEADS + h) * DQd + DNd + 2 * i);
    float2 v = __half22float2(*p);
    *p = __floats2half2_rn(v.x * cs - v.y * sn, v.x * sn + v.y * cs);
}

extern "C" void kernel_launch(void* const* d_in, const int* in_sizes, int n_in,
                              void* d_out, int out_size)
{
    const float* X    = (const float*)d_in[0];
    const float* Wqa  = (const float*)d_in[1];
    const float* Wkva = (const float*)d_in[2];
    const float* Wqb  = (const float*)d_in[3];
    const float* Wkb  = (const float*)d_in[4];
    const float* Wvb  = (const float*)d_in[5];
    const float* Wo   = (const float*)d_in[6];
    float* out = (float*)d_out;

    __half *xh, *wqah, *wkvah, *wqbh, *wkbh, *wvbh, *woh;
    __half *qlath, *kvlath, *qh, *kh, *vth, *aoh;
    float *qlp, *kvlp, *outp;
    cudaGetSymbolAddress((void**)&xh, g_xh);
    cudaGetSymbolAddress((void**)&wqah, g_wqah);
    cudaGetSymbolAddress((void**)&wkvah, g_wkvah);
    cudaGetSymbolAddress((void**)&wqbh, g_wqbh);
    cudaGetSymbolAddress((void**)&wkbh, g_wkbh);
    cudaGetSymbolAddress((void**)&wvbh, g_wvbh);
    cudaGetSymbolAddress((void**)&woh, g_woh);
    cudaGetSymbolAddress((void**)&qlp, g_qlp);
    cudaGetSymbolAddress((void**)&kvlp, g_kvlp);
    cudaGetSymbolAddress((void**)&outp, g_outp);
    cudaGetSymbolAddress((void**)&qlath, g_qlath);
    cudaGetSymbolAddress((void**)&kvlath, g_kvlath);
    cudaGetSymbolAddress((void**)&qh, g_qh);
    cudaGetSymbolAddress((void**)&kh, g_kh);
    cudaGetSymbolAddress((void**)&vth, g_vth);
    cudaGetSymbolAddress((void**)&aoh, g_aoh);

    const int SMEM = 3 * STG_B;  // 98304
    cudaFuncSetAttribute((const void*)hgemm_nt<0, false>,
                         cudaFuncAttributeMaxDynamicSharedMemorySize, SMEM);
    cudaFuncSetAttribute((const void*)hgemm_nt<0, true>,
                         cudaFuncAttributeMaxDynamicSharedMemorySize, SMEM);
    cudaFuncSetAttribute((const void*)hgemm_nt<1, false>,
                         cudaFuncAttributeMaxDynamicSharedMemorySize, SMEM);
    cudaFuncSetAttribute((const void*)hgemm_nt<1, true>,
                         cudaFuncAttributeMaxDynamicSharedMemorySize, SMEM);
    cudaFuncSetAttribute((const void*)flash_attn,
                         cudaFuncAttributeMaxDynamicSharedMemorySize, FA_SMEM);

    const dim3 blk(256);

    // launch 0: fused fp32->fp16 conversion of all inputs
    {
        CvtPtrs p;
        p.s[0] = X;    p.d[0] = xh;
        p.s[1] = Wqa;  p.d[1] = wqah;
        p.s[2] = Wkva; p.d[2] = wkvah;
        p.s[3] = Wqb;  p.d[3] = wqbh;
        p.s[4] = Wkb;  p.d[4] = wkbh;
        p.s[5] = Wvb;  p.d[5] = wvbh;
        p.s[6] = Wo;   p.d[6] = woh;
        cvt_all<<<193536, 256>>>(p);
    }

    // launch 1: kvlat partials (split-K 8 x 896)
    hgemm_nt<0, false><<<dim3(KVLORA / 128, S_LEN / 128, 8), blk, SMEM>>>(
        xh, wkvah, kvlp, DMODEL, DMODEL, DMODEL, KVLORA, 0, 0, (long)S_LEN * KVLORA, 896);
    // launch 2: reduce kvlat
    {
        int n4 = S_LEN * KVLORA / 4;
        reduce_kh<8><<<(n4 + 255) / 256, 256>>>(kvlp, kvlath, n4, (long)n4);
    }
    // launch 3 (ncu capture target, unchanged control): k = kvlath @ Wkb^T
    hgemm_nt<1, false><<<dim3(EQ / 128, S_LEN / 128, 1), blk, SMEM>>>(
        kvlath, wkbh, kh, KVLORA, KVLORA, KVLORA, EQ, 0, 0, 0, 0);
    // launch 4: vt = Wvbh @ kvlath^T  [16384, 1024]
    hgemm_nt<1, false><<<dim3(S_LEN / 128, EV / 128, 1), blk, SMEM>>>(
        wvbh, kvlath, vth, KVLORA, KVLORA, KVLORA, S_LEN, 0, 0, 0, 0);
    // launch 5: qlat partials (split-K 8 x 896) — wave-friendly grid 768
    hgemm_nt<0, false><<<dim3(QLORA / 128, S_LEN / 128, 8), blk, SMEM>>>(
        xh, wqah, qlp, DMODEL, DMODEL, DMODEL, QLORA, 0, 0, (long)S_LEN * QLORA, 896);
    // launch 6: reduce qlat
    {
        int n4 = S_LEN * QLORA / 4;
        reduce_kh<8><<<(n4 + 255) / 256, 256>>>(qlp, qlath, n4, (long)n4);
    }
    // launch 7: q = qlath @ Wqb^T  [1024, 24576]  (SWAP: weight-reuse order)
    hgemm_nt<1, true><<<dim3(S_LEN / 128, EQ / 128, 1), blk, SMEM>>>(
        qlath, wqbh, qh, QLORA, QLORA, QLORA, EQ, 0, 0, 0, 0);

    // launch 8: fused RoPE on q and k
    rope_qk<<<(2 * S_LEN * NHEADS * 32) / 256, 256>>>(qh, kh);

    // launch 9: fused flash attention -> aoh fp16
    flash_attn<<<dim3(S_LEN / 128, NHEADS), blk, FA_SMEM>>>(qh, kh, vth, aoh);

    // launch 10: out-proj partials = aoh @ Wo^T, split-K 4 x 4096 (SWAP)
    // grid 8 x 56 x 4 = 1792 CTAs -> ~6 waves, no half-empty tail.
    hgemm_nt<0, true><<<dim3(S_LEN / 128, DMODEL / 128, 4), blk, SMEM>>>(
        aoh, woh, outp, EV, EV, EV, DMODEL, 0, 0, (long)S_LEN * DMODEL, 4096);
    // launch 11: reduce out partials (fp32)
    {
        int n4 = S_LEN * DMODEL / 4;
        reduce_kf<4><<<(n4 + 255) / 256, 256>>>(outp, out, n4, (long)n4);
    }
}

// round 16
// speedup vs baseline: 1.0086x; 1.0086x over previous
#include <cuda_runtime.h>
#include <cuda_fp16.h>
#include <math.h>
#include <stdint.h>

#define S_LEN 1024
#define NHEADS 128
#define DQd 192
#define DNd 128
#define DVd 128
#define DMODEL 7168
#define QLORA 1536
#define KVLORA 512
#define EQ (NHEADS * DQd)   // 24576
#define EV (NHEADS * DVd)   // 16384

// ---- scratch (__device__ globals; allocation-free rule) ----
__device__ __half g_xh[(size_t)S_LEN * DMODEL];
__device__ __half g_wqah[(size_t)QLORA * DMODEL];
__device__ __half g_wkvah[(size_t)KVLORA * DMODEL];
__device__ __half g_wqbh[(size_t)EQ * QLORA];
__device__ __half g_wkbh[(size_t)EQ * KVLORA];
__device__ __half g_wvbh[(size_t)EV * KVLORA];
__device__ __half g_woh[(size_t)DMODEL * EV];
__device__ float  g_qlp[(size_t)8 * S_LEN * QLORA];
__device__ float  g_kvlp[(size_t)8 * S_LEN * KVLORA];
__device__ __half g_qlath[(size_t)S_LEN * QLORA];
__device__ __half g_kvlath[(size_t)S_LEN * KVLORA];
__device__ __half g_qh[(size_t)S_LEN * EQ];
__device__ __half g_kh[(size_t)S_LEN * EQ];
__device__ __half g_vth[(size_t)EV * S_LEN];        // V^T per head: [h*128+d][s]
__device__ __half g_aoh[(size_t)S_LEN * EV];

__device__ __forceinline__ void cp_async16(uint32_t dst, const void* src) {
    asm volatile("cp.async.cg.shared.global [%0], [%1], 16;\n" :: "r"(dst), "l"(src));
}
#define CP_COMMIT() asm volatile("cp.async.commit_group;\n" ::: "memory")
#define CP_WAIT0()  asm volatile("cp.async.wait_group 0;\n" ::: "memory")
#define CP_WAIT1()  asm volatile("cp.async.wait_group 1;\n" ::: "memory")
#define CP_WAIT2()  asm volatile("cp.async.wait_group 2;\n" ::: "memory")

__device__ __forceinline__ void ldsm_x4(unsigned* r, uint32_t addr) {
    asm volatile("ldmatrix.sync.aligned.m8n8.x4.shared.b16 {%0,%1,%2,%3}, [%4];"
                 : "=r"(r[0]), "=r"(r[1]), "=r"(r[2]), "=r"(r[3]) : "r"(addr));
}
__device__ __forceinline__ void mma_f16(float* d, const unsigned* a, unsigned b0, unsigned b1) {
    asm volatile(
        "mma.sync.aligned.m16n8k16.row.col.f32.f16.f16.f32 "
        "{%0,%1,%2,%3}, {%4,%5,%6,%7}, {%8,%9}, {%0,%1,%2,%3};"
        : "+f"(d[0]), "+f"(d[1]), "+f"(d[2]), "+f"(d[3])
        : "r"(a[0]), "r"(a[1]), "r"(a[2]), "r"(a[3]), "r"(b0), "r"(b1));
}
__device__ __forceinline__ unsigned ph2(float a, float b) {
    __half2 h = __floats2half2_rn(a, b);
    return *(unsigned*)&h;
}

// ---------------------------------------------------------------------------
// C[M,N] = A[M,K] @ B^T (B is [N,K] row-major), fp16 in, fp32 accumulate.
// Block 128x128, kTile 64 halves, 8 warps of 32x64 (m16n8k16 + ldmatrix).
// 3-stage cp.async pipeline (32KB/stage, 96KB total), 2 CTAs/SM.
// OUT: 0 = fp32 C, 1 = fp16 C.  SWAP: m from blockIdx.x (B-reuse order).
// DUAL: blockIdx.x >= xsplit selects second (B2, C2, ldc2, sC2) problem —
//       used to fuse the qlat and kvlat split-K GEMMs into one launch.
// kChunk>0: split-K (z = k-window, C plane z*sC); else z = batch via sA/sB/sC.
// ---------------------------------------------------------------------------
#define KT 64
#define STG_B 32768   // bytes per stage (A 16KB + B 16KB)

template <int OUT, bool SWAP, bool DUAL>
__global__ __launch_bounds__(256, 2) void hgemm_nt(
    const __half* __restrict__ Ag, const __half* __restrict__ Bg, void* __restrict__ Cg,
    int K, int lda, int ldb, int ldc, long sA, long sB, long sC, int kChunk,
    const __half* __restrict__ Bg2, void* __restrict__ Cg2, int ldc2, long sC2, int xsplit)
{
    extern __shared__ char smraw[];
    const uint32_t smb = (uint32_t)__cvta_generic_to_shared(smraw);

    // segment select (DUAL) + tile coords
    const int bx = blockIdx.x;
    const __half* Bbase = Bg;
    void* Cs = Cg;
    int ldcv = ldc;
    long sCv = sC;
    int nx = SWAP ? blockIdx.y : bx;
    if (DUAL && bx >= xsplit) {
        Bbase = Bg2; Cs = Cg2; ldcv = ldc2; sCv = sC2; nx = bx - xsplit;
    }

    const int z = blockIdx.z;
    const __half *A, *B;
    int Keff;
    if (kChunk) { A = Ag + (long)z * kChunk; B = Bbase + (long)z * kChunk; Keff = kChunk; }
    else        { A = Ag + (long)z * sA;     B = Bbase + (long)z * sB;     Keff = K; }
    float*  Cf = (float*)Cs  + (long)z * sCv;
    __half* Ch = (__half*)Cs + (long)z * sCv;

    const int m0 = (SWAP ? bx : blockIdx.y) * 128;
    const int n0 = nx * 128;
    const int t = threadIdx.x, w = t >> 5, lane = t & 31;
    const int wm = w >> 1, wn = w & 1;

    const int srow = t >> 1, c0 = (t & 1) * 4;
    const int rx = srow & 7;
    const __half* Asrc = A + (long)(m0 + srow) * lda + c0 * 8;
    const __half* Bsrc = B + (long)(n0 + srow) * ldb + c0 * 8;
    const uint32_t sAr = smb + srow * 128;
    const uint32_t sBr = smb + 16384 + srow * 128;

    float acc[2][8][4] = {};
    const int niter = Keff / KT;

#pragma unroll
    for (int i = 0; i < 4; ++i) {
        cp_async16(sAr + (((c0 + i) ^ rx) << 4), Asrc + i * 8);
        cp_async16(sBr + (((c0 + i) ^ rx) << 4), Bsrc + i * 8);
    }
    CP_COMMIT();
    if (niter > 1) {
#pragma unroll
        for (int i = 0; i < 4; ++i) {
            cp_async16(sAr + STG_B + (((c0 + i) ^ rx) << 4), Asrc + KT + i * 8);
            cp_async16(sBr + STG_B + (((c0 + i) ^ rx) << 4), Bsrc + KT + i * 8);
        }
        CP_COMMIT();
    }

    const int a_r = (lane & 7) + ((lane >> 3) & 1) * 8;
    const int a_c = lane >> 4;
    const int b_r = (lane & 7) + ((lane >> 4) & 1) * 8;
    const int b_c = (lane >> 3) & 1;

    int stage = 0;
    for (int it = 0; it < niter; ++it) {
        if (it + 1 < niter) { CP_WAIT1(); } else { CP_WAIT0(); }
        __syncthreads();

        if (it + 2 < niter) {
            int ns = stage + 2; if (ns >= 3) ns -= 3;
            const uint32_t off = ns * STG_B;
            const int k0 = (it + 2) * KT;
#pragma unroll
            for (int i = 0; i < 4; ++i) {
                cp_async16(sAr + off + (((c0 + i) ^ rx) << 4), Asrc + k0 + i * 8);
                cp_async16(sBr + off + (((c0 + i) ^ rx) << 4), Bsrc + k0 + i * 8);
            }
            CP_COMMIT();
        }

        const uint32_t saA = smb + stage * STG_B;
        const uint32_t saB = saA + 16384;

#pragma unroll
        for (int kc = 0; kc < 4; ++kc) {
            unsigned af[2][4];
#pragma unroll
            for (int mt = 0; mt < 2; ++mt) {
                const int r = wm * 32 + mt * 16 + a_r;
                ldsm_x4(af[mt], saA + r * 128 + (((kc * 2 + a_c) ^ (r & 7)) << 4));
            }
#pragma unroll
            for (int ntt = 0; ntt < 4; ++ntt) {
                const int r = wn * 64 + ntt * 16 + b_r;
                unsigned bf[4];
                ldsm_x4(bf, saB + r * 128 + (((kc * 2 + b_c) ^ (r & 7)) << 4));
#pragma unroll
                for (int mt = 0; mt < 2; ++mt) {
                    mma_f16(acc[mt][2 * ntt],     af[mt], bf[0], bf[1]);
                    mma_f16(acc[mt][2 * ntt + 1], af[mt], bf[2], bf[3]);
                }
            }
        }
        ++stage; if (stage == 3) stage = 0;
    }

    const int g = lane >> 2, tq = lane & 3;
#pragma unroll
    for (int mt = 0; mt < 2; ++mt) {
        const int rr = m0 + wm * 32 + mt * 16 + g;
#pragma unroll
        for (int nt = 0; nt < 8; ++nt) {
            const int cc = n0 + wn * 64 + nt * 8 + tq * 2;
            if (OUT == 0) {
                *(float2*)(Cf + (long)rr * ldcv + cc) =
                    make_float2(acc[mt][nt][0], acc[mt][nt][1]);
                *(float2*)(Cf + (long)(rr + 8) * ldcv + cc) =
                    make_float2(acc[mt][nt][2], acc[mt][nt][3]);
            } else {
                *(__half2*)(Ch + (long)rr * ldcv + cc) =
                    __floats2half2_rn(acc[mt][nt][0], acc[mt][nt][1]);
                *(__half2*)(Ch + (long)(rr + 8) * ldcv + cc) =
                    __floats2half2_rn(acc[mt][nt][2], acc[mt][nt][3]);
            }
        }
    }
}

// ---------------------------------------------------------------------------
// Fused flash attention. Grid (8 q-blocks, 128 heads), 256 threads (8 warps).
// Split prefetch: K(kb+2) issued right after QK^T consumes K(kb) (mid sync);
// V(kb+2) issued after PV consumes V(kb). Loads overlap softmax/PV/next-QK.
// Per-thread group ledger: prologue commits {Q,K0,V0},{K1,V1}; each block
// commits K then V -> at block kb (1..6) wait_group 2 guarantees K(kb),V(kb).
// ---------------------------------------------------------------------------
#define FA_KSTG 49152
#define FA_VSTG 32768
#define FA_SMEM (FA_KSTG * 3 + FA_VSTG * 2)   // 212992

__global__ __launch_bounds__(256, 1) void flash_attn(
    const __half* __restrict__ Qg,   // [S][H][192]
    const __half* __restrict__ Kg,   // [S][H][192]
    const __half* __restrict__ Vt,   // [H*128][S]
    __half* __restrict__ Og)         // [S][H*128]
{
    extern __shared__ char smraw[];
    const uint32_t smb = (uint32_t)__cvta_generic_to_shared(smraw);
    const uint32_t Qs  = smb;
    const uint32_t Ks0 = smb + FA_KSTG;
    const uint32_t Vs0 = smb + FA_KSTG * 3;

    const int qb = blockIdx.x * 128;
    const int h  = blockIdx.y;
    const int t = threadIdx.x, w = t >> 5, lane = t & 31;
    const int g = lane >> 2, tq = lane & 3;

    const int srow = t >> 1, rx = srow & 7;
    const int cbase = (t & 1) * 12;
    const int vcbase = (t & 1) * 8;
    const __half* Qsrc = Qg + ((long)(qb + srow) * NHEADS + h) * DQd;
    const __half* Ksrc = Kg + ((long)srow * NHEADS + h) * DQd;
    const __half* Vsrc = Vt + (long)(h * 128 + srow) * S_LEN;
    const long KBLK = (long)128 * NHEADS * DQd;

    // prologue: G1 = {Q, K0, V0}; G2 = {K1, V1}
#pragma unroll
    for (int i = 0; i < 12; ++i) {
        const int c = cbase + i;
        cp_async16(Qs  + srow * 384 + ((c ^ rx) << 4), Qsrc + c * 8);
        cp_async16(Ks0 + srow * 384 + ((c ^ rx) << 4), Ksrc + c * 8);
    }
#pragma unroll
    for (int i = 0; i < 8; ++i) {
        const int c = vcbase + i;
        cp_async16(Vs0 + srow * 256 + ((c ^ rx) << 4), Vsrc + c * 8);
    }
    CP_COMMIT();
#pragma unroll
    for (int i = 0; i < 12; ++i) {
        const int c = cbase + i;
        cp_async16(Ks0 + FA_KSTG + srow * 384 + ((c ^ rx) << 4), Ksrc + KBLK + c * 8);
    }
#pragma unroll
    for (int i = 0; i < 8; ++i) {
        const int c = vcbase + i;
        cp_async16(Vs0 + FA_VSTG + srow * 256 + ((c ^ rx) << 4), Vsrc + 128 + c * 8);
    }
    CP_COMMIT();

    const int a_r = (lane & 7) + ((lane >> 3) & 1) * 8;
    const int a_c = lane >> 4;
    const int b_r = (lane & 7) + ((lane >> 4) & 1) * 8;
    const int b_c = (lane >> 3) & 1;

    float oacc[16][4] = {};
    float m0 = -1e30f, m1 = -1e30f, l0 = 0.f, l1 = 0.f;
    const float ksc = 0.07216878364870323f * 1.4426950408889634f;

    for (int kb = 0; kb < 8; ++kb) {
        if (kb == 0)      { CP_WAIT1(); }
        else if (kb == 7) { CP_WAIT0(); }
        else              { CP_WAIT2(); }
        const uint32_t Kst = Ks0 + (kb & 1) * FA_KSTG;
        const uint32_t Vst = Vs0 + (kb & 1) * FA_VSTG;

        // --- QK^T ---
        float sacc[16][4] = {};
#pragma unroll
        for (int kc = 0; kc < 12; ++kc) {
            unsigned aq[4];
            {
                const int r = w * 16 + a_r;
                ldsm_x4(aq, Qs + r * 384 + (((kc * 2 + a_c) ^ (r & 7)) << 4));
            }
#pragma unroll
            for (int ntt = 0; ntt < 8; ++ntt) {
                const int r = ntt * 16 + b_r;
                unsigned bk[4];
                ldsm_x4(bk, Kst + r * 384 + (((kc * 2 + b_c) ^ (r & 7)) << 4));
                mma_f16(sacc[2 * ntt],     aq, bk[0], bk[1]);
                mma_f16(sacc[2 * ntt + 1], aq, bk[2], bk[3]);
            }
        }
        __syncthreads();                 // all warps done reading K(kb)
        if (kb + 2 < 8) {                // K(kb+2) overlaps softmax + PV
            const long koff = (long)(kb + 2) * 128;
#pragma unroll
            for (int i = 0; i < 12; ++i) {
                const int c = cbase + i;
                cp_async16(Kst + srow * 384 + ((c ^ rx) << 4),
                           Ksrc + koff * NHEADS * DQd + c * 8);
            }
            CP_COMMIT();
        }

        // --- online softmax ---
        float bm0 = -1e30f, bm1 = -1e30f;
#pragma unroll
        for (int nt = 0; nt < 16; ++nt) {
            bm0 = fmaxf(bm0, fmaxf(sacc[nt][0], sacc[nt][1]));
            bm1 = fmaxf(bm1, fmaxf(sacc[nt][2], sacc[nt][3]));
        }
        bm0 = fmaxf(bm0, __shfl_xor_sync(0xffffffffu, bm0, 1));
        bm0 = fmaxf(bm0, __shfl_xor_sync(0xffffffffu, bm0, 2));
        bm1 = fmaxf(bm1, __shfl_xor_sync(0xffffffffu, bm1, 1));
        bm1 = fmaxf(bm1, __shfl_xor_sync(0xffffffffu, bm1, 2));
        const float mn0 = fmaxf(m0, bm0), mn1 = fmaxf(m1, bm1);
        const float al0 = exp2f(ksc * (m0 - mn0));
        const float al1 = exp2f(ksc * (m1 - mn1));
        l0 *= al0; l1 *= al1;
#pragma unroll
        for (int nt = 0; nt < 16; ++nt) {
            oacc[nt][0] *= al0; oacc[nt][1] *= al0;
            oacc[nt][2] *= al1; oacc[nt][3] *= al1;
        }
        m0 = mn0; m1 = mn1;

        unsigned pa[8][4];
        float s0 = 0.f, s1 = 0.f;
#pragma unroll
        for (int j = 0; j < 8; ++j) {
            const float p00 = exp2f(ksc * (sacc[2*j][0] - mn0));
            const float p01 = exp2f(ksc * (sacc[2*j][1] - mn0));
            const float p02 = exp2f(ksc * (sacc[2*j][2] - mn1));
            const float p03 = exp2f(ksc * (sacc[2*j][3] - mn1));
            const float p10 = exp2f(ksc * (sacc[2*j+1][0] - mn0));
            const float p11 = exp2f(ksc * (sacc[2*j+1][1] - mn0));
            const float p12 = exp2f(ksc * (sacc[2*j+1][2] - mn1));
            const float p13 = exp2f(ksc * (sacc[2*j+1][3] - mn1));
            s0 += p00 + p01 + p10 + p11;
            s1 += p02 + p03 + p12 + p13;
            pa[j][0] = ph2(p00, p01);
            pa[j][1] = ph2(p02, p03);
            pa[j][2] = ph2(p10, p11);
            pa[j][3] = ph2(p12, p13);
        }
        s0 += __shfl_xor_sync(0xffffffffu, s0, 1);
        s0 += __shfl_xor_sync(0xffffffffu, s0, 2);
        s1 += __shfl_xor_sync(0xffffffffu, s1, 1);
        s1 += __shfl_xor_sync(0xffffffffu, s1, 2);
        l0 += s0; l1 += s1;

        // --- P @ V ---
#pragma unroll
        for (int j = 0; j < 8; ++j) {
#pragma unroll
            for (int nt2 = 0; nt2 < 8; ++nt2) {
                const int r = nt2 * 16 + b_r;
                unsigned bv[4];
                ldsm_x4(bv, Vst + r * 256 + (((j * 2 + b_c) ^ (r & 7)) << 4));
                mma_f16(oacc[2 * nt2],     pa[j], bv[0], bv[1]);
                mma_f16(oacc[2 * nt2 + 1], pa[j], bv[2], bv[3]);
            }
        }
        __syncthreads();                 // all warps done reading V(kb)
        if (kb + 2 < 8) {                // V(kb+2) overlaps next QK
            const long koff = (long)(kb + 2) * 128;
#pragma unroll
            for (int i = 0; i < 8; ++i) {
                const int c = vcbase + i;
                cp_async16(Vst + srow * 256 + ((c ^ rx) << 4), Vsrc + koff + c * 8);
            }
            CP_COMMIT();
        }
    }

    const float i0 = 1.f / l0, i1 = 1.f / l1;
    const int r0 = qb + w * 16 + g;
    __half* orow0 = Og + (long)r0 * EV + h * 128;
    __half* orow1 = orow0 + (long)8 * EV;
#pragma unroll
    for (int nt = 0; nt < 16; ++nt) {
        *(__half2*)(orow0 + nt * 8 + tq * 2) =
            __floats2half2_rn(oacc[nt][0] * i0, oacc[nt][1] * i0);
        *(__half2*)(orow1 + nt * 8 + tq * 2) =
            __floats2half2_rn(oacc[nt][2] * i1, oacc[nt][3] * i1);
    }
}

// ---- fused fp32 -> fp16 conversion of all 7 inputs (ONE launch) ----
struct CvtPtrs { const float* s[7]; __half* d[7]; };
__global__ void cvt_all(CvtPtrs p)
{
    const long seg[7] = {1835008, 2752512, 917504, 9437184, 3145728, 2097152, 29360128};
    long i = (long)blockIdx.x * blockDim.x + threadIdx.x;
    long rem = i;
    int j = 0;
#pragma unroll
    for (int k = 0; k < 7; ++k) {
        if (j == k && rem >= seg[k]) { rem -= seg[k]; j = k + 1; }
    }
    if (j >= 7) return;
    float4 v = ((const float4*)p.s[j])[rem];
    __half2* dst = (__half2*)p.d[j] + rem * 2;
    dst[0] = __floats2half2_rn(v.x, v.y);
    dst[1] = __floats2half2_rn(v.z, v.w);
}

// ---- fused split-K reduce for qlat (8 planes) and kvlat (8 planes) ----
#define QN4  (S_LEN * QLORA / 4)    // 393216
#define KVN4 (S_LEN * KVLORA / 4)   // 131072
__global__ void reduce_lat(const float* __restrict__ qlp, const float* __restrict__ kvlp,
                           __half* __restrict__ qlath, __half* __restrict__ kvlath)
{
    int i = blockIdx.x * blockDim.x + threadIdx.x;
    const float* in;
    __half* out;
    long idx, stride;
    if (i < QN4)             { in = qlp;  out = qlath;  idx = i;        stride = QN4;  }
    else if (i < QN4 + KVN4) { in = kvlp; out = kvlath; idx = i - QN4;  stride = KVN4; }
    else return;
    float4 s = ((const float4*)in)[idx];
#pragma unroll
    for (int p = 1; p < 8; ++p) {
        float4 v = ((const float4*)in)[idx + (long)p * stride];
        s.x += v.x; s.y += v.y; s.z += v.z; s.w += v.w;
    }
    __half2* d = (__half2*)out + idx * 2;
    d[0] = __floats2half2_rn(s.x, s.y);
    d[1] = __floats2half2_rn(s.z, s.w);
}

// Fused interleaved RoPE over dims [128,192) for BOTH q and k.
__global__ void rope_qk(__half* __restrict__ Q, __half* __restrict__ K)
{
    long idx = (long)blockIdx.x * blockDim.x + threadIdx.x;
    if (idx >= (long)2 * S_LEN * NHEADS * 32) return;
    __half* X = (idx >> 22) ? K : Q;
    long id = idx & 0x3FFFFF;
    int i = (int)(id & 31);
    int h = (int)((id >> 5) & (NHEADS - 1));
    int s = (int)(id >> 12);

    int m = (2 * i) & 31;
    float invf = (float)pow(10000.0, -(double)m / 32.0);
    float ang = (float)s * invf;
    float sn, cs;
    sincosf(ang, &sn, &cs);

    __half2* p = (__half2*)(X + ((long)s * NHEADS + h) * DQd + DNd + 2 * i);
    float2 v = __half22float2(*p);
    *p = __floats2half2_rn(v.x * cs - v.y * sn, v.x * sn + v.y * cs);
}

extern "C" void kernel_launch(void* const* d_in, const int* in_sizes, int n_in,
                              void* d_out, int out_size)
{
    const float* X    = (const float*)d_in[0];
    const float* Wqa  = (const float*)d_in[1];
    const float* Wkva = (const float*)d_in[2];
    const float* Wqb  = (const float*)d_in[3];
    const float* Wkb  = (const float*)d_in[4];
    const float* Wvb  = (const float*)d_in[5];
    const float* Wo   = (const float*)d_in[6];
    float* out = (float*)d_out;

    __half *xh, *wqah, *wkvah, *wqbh, *wkbh, *wvbh, *woh;
    __half *qlath, *kvlath, *qh, *kh, *vth, *aoh;
    float *qlp, *kvlp;
    cudaGetSymbolAddress((void**)&xh, g_xh);
    cudaGetSymbolAddress((void**)&wqah, g_wqah);
    cudaGetSymbolAddress((void**)&wkvah, g_wkvah);
    cudaGetSymbolAddress((void**)&wqbh, g_wqbh);
    cudaGetSymbolAddress((void**)&wkbh, g_wkbh);
    cudaGetSymbolAddress((void**)&wvbh, g_wvbh);
    cudaGetSymbolAddress((void**)&woh, g_woh);
    cudaGetSymbolAddress((void**)&qlp, g_qlp);
    cudaGetSymbolAddress((void**)&kvlp, g_kvlp);
    cudaGetSymbolAddress((void**)&qlath, g_qlath);
    cudaGetSymbolAddress((void**)&kvlath, g_kvlath);
    cudaGetSymbolAddress((void**)&qh, g_qh);
    cudaGetSymbolAddress((void**)&kh, g_kh);
    cudaGetSymbolAddress((void**)&vth, g_vth);
    cudaGetSymbolAddress((void**)&aoh, g_aoh);

    const int SMEM = 3 * STG_B;  // 98304
    cudaFuncSetAttribute((const void*)hgemm_nt<0, false, true>,
                         cudaFuncAttributeMaxDynamicSharedMemorySize, SMEM);
    cudaFuncSetAttribute((const void*)hgemm_nt<0, true, false>,
                         cudaFuncAttributeMaxDynamicSharedMemorySize, SMEM);
    cudaFuncSetAttribute((const void*)hgemm_nt<1, false, false>,
                         cudaFuncAttributeMaxDynamicSharedMemorySize, SMEM);
    cudaFuncSetAttribute((const void*)hgemm_nt<1, true, false>,
                         cudaFuncAttributeMaxDynamicSharedMemorySize, SMEM);
    cudaFuncSetAttribute((const void*)flash_attn,
                         cudaFuncAttributeMaxDynamicSharedMemorySize, FA_SMEM);

    const dim3 blk(256);

    // launch 0: fused fp32->fp16 conversion of all inputs
    {
        CvtPtrs p;
        p.s[0] = X;    p.d[0] = xh;
        p.s[1] = Wqa;  p.d[1] = wqah;
        p.s[2] = Wkva; p.d[2] = wkvah;
        p.s[3] = Wqb;  p.d[3] = wqbh;
        p.s[4] = Wkb;  p.d[4] = wkbh;
        p.s[5] = Wvb;  p.d[5] = wvbh;
        p.s[6] = Wo;   p.d[6] = woh;
        cvt_all<<<193536, 256>>>(p);
    }

    // launch 1: FUSED qlat + kvlat partials (split-K 8 x 896 each)
    // x<12 -> qlat tile (N=1536), x>=12 -> kvlat tile (N=512). Grid 1024 CTAs.
    hgemm_nt<0, false, true><<<dim3(16, S_LEN / 128, 8), blk, SMEM>>>(
        xh, wqah, qlp, DMODEL, DMODEL, DMODEL, QLORA, 0, 0, (long)S_LEN * QLORA, 896,
        wkvah, kvlp, KVLORA, (long)S_LEN * KVLORA, 12);
    // launch 2: fused reduce (qlat + kvlat)
    reduce_lat<<<(QN4 + KVN4) / 256, 256>>>(qlp, kvlp, qlath, kvlath);

    // launch 3 (ncu capture target, unchanged control): k = kvlath @ Wkb^T
    hgemm_nt<1, false, false><<<dim3(EQ / 128, S_LEN / 128, 1), blk, SMEM>>>(
        kvlath, wkbh, kh, KVLORA, KVLORA, KVLORA, EQ, 0, 0, 0, 0,
        nullptr, nullptr, 0, 0, 0);
    // launch 4: vt = Wvbh @ kvlath^T  [16384, 1024]
    hgemm_nt<1, false, false><<<dim3(S_LEN / 128, EV / 128, 1), blk, SMEM>>>(
        wvbh, kvlath, vth, KVLORA, KVLORA, KVLORA, S_LEN, 0, 0, 0, 0,
        nullptr, nullptr, 0, 0, 0);
    // launch 5: q = qlath @ Wqb^T  [1024, 24576]  (SWAP: weight-reuse order)
    hgemm_nt<1, true, false><<<dim3(S_LEN / 128, EQ / 128, 1), blk, SMEM>>>(
        qlath, wqbh, qh, QLORA, QLORA, QLORA, EQ, 0, 0, 0, 0,
        nullptr, nullptr, 0, 0, 0);

    // launch 6: fused RoPE on q and k
    rope_qk<<<(2 * S_LEN * NHEADS * 32) / 256, 256>>>(qh, kh);

    // launch 7: fused flash attention -> aoh fp16
    flash_attn<<<dim3(S_LEN / 128, NHEADS), blk, FA_SMEM>>>(qh, kh, vth, aoh);

    // launch 8: out = attn_out @ Wo^T  [1024, 7168] fp32  (SWAP, direct)
    hgemm_nt<0, true, false><<<dim3(S_LEN / 128, DMODEL / 128, 1), blk, SMEM>>>(
        aoh, woh, out, EV, EV, EV, DMODEL, 0, 0, 0, 0,
        nullptr, nullptr, 0, 0, 0);
}

// round 17
// speedup vs baseline: 1.9317x; 1.9152x over previous
#include <cuda_runtime.h>
#include <cuda_fp16.h>
#include <math.h>
#include <stdint.h>

#define S_LEN 1024
#define NHEADS 128
#define DQd 192
#define DNd 128
#define DVd 128
#define DMODEL 7168
#define QLORA 1536
#define KVLORA 512
#define EQ (NHEADS * DQd)   // 24576
#define EV (NHEADS * DVd)   // 16384

// ---- scratch (__device__ globals; allocation-free rule) ----
__device__ __half g_xh[(size_t)S_LEN * DMODEL];
__device__ __half g_wqah[(size_t)QLORA * DMODEL];
__device__ __half g_wkvah[(size_t)KVLORA * DMODEL];
__device__ __half g_wqbh[(size_t)EQ * QLORA];
__device__ __half g_wkbh[(size_t)EQ * KVLORA];
__device__ __half g_wvbh[(size_t)EV * KVLORA];
__device__ __half g_woh[(size_t)DMODEL * EV];
__device__ float  g_qlp[(size_t)8 * S_LEN * QLORA];
__device__ float  g_kvlp[(size_t)8 * S_LEN * KVLORA];
__device__ __half g_qlath[(size_t)S_LEN * QLORA];
__device__ __half g_kvlath[(size_t)S_LEN * KVLORA];
__device__ __half g_qh[(size_t)S_LEN * EQ];
__device__ __half g_kh[(size_t)S_LEN * EQ];
__device__ __half g_vth[(size_t)EV * S_LEN];        // V^T per head: [h*128+d][s]
__device__ __half g_aoh[(size_t)S_LEN * EV];
__device__ float2 g_rtab[(size_t)S_LEN * 32];       // RoPE cos/sin table

__device__ __forceinline__ void cp_async16(uint32_t dst, const void* src) {
    asm volatile("cp.async.cg.shared.global [%0], [%1], 16;\n" :: "r"(dst), "l"(src));
}
#define CP_COMMIT() asm volatile("cp.async.commit_group;\n" ::: "memory")
#define CP_WAIT0()  asm volatile("cp.async.wait_group 0;\n" ::: "memory")
#define CP_WAIT1()  asm volatile("cp.async.wait_group 1;\n" ::: "memory")
#define CP_WAIT2()  asm volatile("cp.async.wait_group 2;\n" ::: "memory")

__device__ __forceinline__ void ldsm_x4(unsigned* r, uint32_t addr) {
    asm volatile("ldmatrix.sync.aligned.m8n8.x4.shared.b16 {%0,%1,%2,%3}, [%4];"
                 : "=r"(r[0]), "=r"(r[1]), "=r"(r[2]), "=r"(r[3]) : "r"(addr));
}
__device__ __forceinline__ void mma_f16(float* d, const unsigned* a, unsigned b0, unsigned b1) {
    asm volatile(
        "mma.sync.aligned.m16n8k16.row.col.f32.f16.f16.f32 "
        "{%0,%1,%2,%3}, {%4,%5,%6,%7}, {%8,%9}, {%0,%1,%2,%3};"
        : "+f"(d[0]), "+f"(d[1]), "+f"(d[2]), "+f"(d[3])
        : "r"(a[0]), "r"(a[1]), "r"(a[2]), "r"(a[3]), "r"(b0), "r"(b1));
}
__device__ __forceinline__ unsigned ph2(float a, float b) {
    __half2 h = __floats2half2_rn(a, b);
    return *(unsigned*)&h;
}

// ---------------------------------------------------------------------------
// hgemm_nt: unchanged from R16 (best passing config).
// ---------------------------------------------------------------------------
#define KT 64
#define STG_B 32768   // bytes per stage (A 16KB + B 16KB)

template <int OUT, bool SWAP, bool DUAL>
__global__ __launch_bounds__(256, 2) void hgemm_nt(
    const __half* __restrict__ Ag, const __half* __restrict__ Bg, void* __restrict__ Cg,
    int K, int lda, int ldb, int ldc, long sA, long sB, long sC, int kChunk,
    const __half* __restrict__ Bg2, void* __restrict__ Cg2, int ldc2, long sC2, int xsplit)
{
    extern __shared__ char smraw[];
    const uint32_t smb = (uint32_t)__cvta_generic_to_shared(smraw);

    const int bx = blockIdx.x;
    const __half* Bbase = Bg;
    void* Cs = Cg;
    int ldcv = ldc;
    long sCv = sC;
    int nx = SWAP ? blockIdx.y : bx;
    if (DUAL && bx >= xsplit) {
        Bbase = Bg2; Cs = Cg2; ldcv = ldc2; sCv = sC2; nx = bx - xsplit;
    }

    const int z = blockIdx.z;
    const __half *A, *B;
    int Keff;
    if (kChunk) { A = Ag + (long)z * kChunk; B = Bbase + (long)z * kChunk; Keff = kChunk; }
    else        { A = Ag + (long)z * sA;     B = Bbase + (long)z * sB;     Keff = K; }
    float*  Cf = (float*)Cs  + (long)z * sCv;
    __half* Ch = (__half*)Cs + (long)z * sCv;

    const int m0 = (SWAP ? bx : blockIdx.y) * 128;
    const int n0 = nx * 128;
    const int t = threadIdx.x, w = t >> 5, lane = t & 31;
    const int wm = w >> 1, wn = w & 1;

    const int srow = t >> 1, c0 = (t & 1) * 4;
    const int rx = srow & 7;
    const __half* Asrc = A + (long)(m0 + srow) * lda + c0 * 8;
    const __half* Bsrc = B + (long)(n0 + srow) * ldb + c0 * 8;
    const uint32_t sAr = smb + srow * 128;
    const uint32_t sBr = smb + 16384 + srow * 128;

    float acc[2][8][4] = {};
    const int niter = Keff / KT;

#pragma unroll
    for (int i = 0; i < 4; ++i) {
        cp_async16(sAr + (((c0 + i) ^ rx) << 4), Asrc + i * 8);
        cp_async16(sBr + (((c0 + i) ^ rx) << 4), Bsrc + i * 8);
    }
    CP_COMMIT();
    if (niter > 1) {
#pragma unroll
        for (int i = 0; i < 4; ++i) {
            cp_async16(sAr + STG_B + (((c0 + i) ^ rx) << 4), Asrc + KT + i * 8);
            cp_async16(sBr + STG_B + (((c0 + i) ^ rx) << 4), Bsrc + KT + i * 8);
        }
        CP_COMMIT();
    }

    const int a_r = (lane & 7) + ((lane >> 3) & 1) * 8;
    const int a_c = lane >> 4;
    const int b_r = (lane & 7) + ((lane >> 4) & 1) * 8;
    const int b_c = (lane >> 3) & 1;

    int stage = 0;
    for (int it = 0; it < niter; ++it) {
        if (it + 1 < niter) { CP_WAIT1(); } else { CP_WAIT0(); }
        __syncthreads();

        if (it + 2 < niter) {
            int ns = stage + 2; if (ns >= 3) ns -= 3;
            const uint32_t off = ns * STG_B;
            const int k0 = (it + 2) * KT;
#pragma unroll
            for (int i = 0; i < 4; ++i) {
                cp_async16(sAr + off + (((c0 + i) ^ rx) << 4), Asrc + k0 + i * 8);
                cp_async16(sBr + off + (((c0 + i) ^ rx) << 4), Bsrc + k0 + i * 8);
            }
            CP_COMMIT();
        }

        const uint32_t saA = smb + stage * STG_B;
        const uint32_t saB = saA + 16384;

#pragma unroll
        for (int kc = 0; kc < 4; ++kc) {
            unsigned af[2][4];
#pragma unroll
            for (int mt = 0; mt < 2; ++mt) {
                const int r = wm * 32 + mt * 16 + a_r;
                ldsm_x4(af[mt], saA + r * 128 + (((kc * 2 + a_c) ^ (r & 7)) << 4));
            }
#pragma unroll
            for (int ntt = 0; ntt < 4; ++ntt) {
                const int r = wn * 64 + ntt * 16 + b_r;
                unsigned bf[4];
                ldsm_x4(bf, saB + r * 128 + (((kc * 2 + b_c) ^ (r & 7)) << 4));
#pragma unroll
                for (int mt = 0; mt < 2; ++mt) {
                    mma_f16(acc[mt][2 * ntt],     af[mt], bf[0], bf[1]);
                    mma_f16(acc[mt][2 * ntt + 1], af[mt], bf[2], bf[3]);
                }
            }
        }
        ++stage; if (stage == 3) stage = 0;
    }

    const int g = lane >> 2, tq = lane & 3;
#pragma unroll
    for (int mt = 0; mt < 2; ++mt) {
        const int rr = m0 + wm * 32 + mt * 16 + g;
#pragma unroll
        for (int nt = 0; nt < 8; ++nt) {
            const int cc = n0 + wn * 64 + nt * 8 + tq * 2;
            if (OUT == 0) {
                *(float2*)(Cf + (long)rr * ldcv + cc) =
                    make_float2(acc[mt][nt][0], acc[mt][nt][1]);
                *(float2*)(Cf + (long)(rr + 8) * ldcv + cc) =
                    make_float2(acc[mt][nt][2], acc[mt][nt][3]);
            } else {
                *(__half2*)(Ch + (long)rr * ldcv + cc) =
                    __floats2half2_rn(acc[mt][nt][0], acc[mt][nt][1]);
                *(__half2*)(Ch + (long)(rr + 8) * ldcv + cc) =
                    __floats2half2_rn(acc[mt][nt][2], acc[mt][nt][3]);
            }
        }
    }
}

// ---------------------------------------------------------------------------
// Fused flash attention (unchanged from R16 passing version).
// ---------------------------------------------------------------------------
#define FA_KSTG 49152
#define FA_VSTG 32768
#define FA_SMEM (FA_KSTG * 3 + FA_VSTG * 2)   // 212992

__global__ __launch_bounds__(256, 1) void flash_attn(
    const __half* __restrict__ Qg,   // [S][H][192]
    const __half* __restrict__ Kg,   // [S][H][192]
    const __half* __restrict__ Vt,   // [H*128][S]
    __half* __restrict__ Og)         // [S][H*128]
{
    extern __shared__ char smraw[];
    const uint32_t smb = (uint32_t)__cvta_generic_to_shared(smraw);
    const uint32_t Qs  = smb;
    const uint32_t Ks0 = smb + FA_KSTG;
    const uint32_t Vs0 = smb + FA_KSTG * 3;

    const int qb = blockIdx.x * 128;
    const int h  = blockIdx.y;
    const int t = threadIdx.x, w = t >> 5, lane = t & 31;
    const int g = lane >> 2, tq = lane & 3;

    const int srow = t >> 1, rx = srow & 7;
    const int cbase = (t & 1) * 12;
    const int vcbase = (t & 1) * 8;
    const __half* Qsrc = Qg + ((long)(qb + srow) * NHEADS + h) * DQd;
    const __half* Ksrc = Kg + ((long)srow * NHEADS + h) * DQd;
    const __half* Vsrc = Vt + (long)(h * 128 + srow) * S_LEN;
    const long KBLK = (long)128 * NHEADS * DQd;

#pragma unroll
    for (int i = 0; i < 12; ++i) {
        const int c = cbase + i;
        cp_async16(Qs  + srow * 384 + ((c ^ rx) << 4), Qsrc + c * 8);
        cp_async16(Ks0 + srow * 384 + ((c ^ rx) << 4), Ksrc + c * 8);
    }
#pragma unroll
    for (int i = 0; i < 8; ++i) {
        const int c = vcbase + i;
        cp_async16(Vs0 + srow * 256 + ((c ^ rx) << 4), Vsrc + c * 8);
    }
    CP_COMMIT();
#pragma unroll
    for (int i = 0; i < 12; ++i) {
        const int c = cbase + i;
        cp_async16(Ks0 + FA_KSTG + srow * 384 + ((c ^ rx) << 4), Ksrc + KBLK + c * 8);
    }
#pragma unroll
    for (int i = 0; i < 8; ++i) {
        const int c = vcbase + i;
        cp_async16(Vs0 + FA_VSTG + srow * 256 + ((c ^ rx) << 4), Vsrc + 128 + c * 8);
    }
    CP_COMMIT();

    const int a_r = (lane & 7) + ((lane >> 3) & 1) * 8;
    const int a_c = lane >> 4;
    const int b_r = (lane & 7) + ((lane >> 4) & 1) * 8;
    const int b_c = (lane >> 3) & 1;

    float oacc[16][4] = {};
    float m0 = -1e30f, m1 = -1e30f, l0 = 0.f, l1 = 0.f;
    const float ksc = 0.07216878364870323f * 1.4426950408889634f;

    for (int kb = 0; kb < 8; ++kb) {
        if (kb == 0)      { CP_WAIT1(); }
        else if (kb == 7) { CP_WAIT0(); }
        else              { CP_WAIT2(); }
        const uint32_t Kst = Ks0 + (kb & 1) * FA_KSTG;
        const uint32_t Vst = Vs0 + (kb & 1) * FA_VSTG;

        float sacc[16][4] = {};
#pragma unroll
        for (int kc = 0; kc < 12; ++kc) {
            unsigned aq[4];
            {
                const int r = w * 16 + a_r;
                ldsm_x4(aq, Qs + r * 384 + (((kc * 2 + a_c) ^ (r & 7)) << 4));
            }
#pragma unroll
            for (int ntt = 0; ntt < 8; ++ntt) {
                const int r = ntt * 16 + b_r;
                unsigned bk[4];
                ldsm_x4(bk, Kst + r * 384 + (((kc * 2 + b_c) ^ (r & 7)) << 4));
                mma_f16(sacc[2 * ntt],     aq, bk[0], bk[1]);
                mma_f16(sacc[2 * ntt + 1], aq, bk[2], bk[3]);
            }
        }
        __syncthreads();
        if (kb + 2 < 8) {
            const long koff = (long)(kb + 2) * 128;
#pragma unroll
            for (int i = 0; i < 12; ++i) {
                const int c = cbase + i;
                cp_async16(Kst + srow * 384 + ((c ^ rx) << 4),
                           Ksrc + koff * NHEADS * DQd + c * 8);
            }
            CP_COMMIT();
        }

        float bm0 = -1e30f, bm1 = -1e30f;
#pragma unroll
        for (int nt = 0; nt < 16; ++nt) {
            bm0 = fmaxf(bm0, fmaxf(sacc[nt][0], sacc[nt][1]));
            bm1 = fmaxf(bm1, fmaxf(sacc[nt][2], sacc[nt][3]));
        }
        bm0 = fmaxf(bm0, __shfl_xor_sync(0xffffffffu, bm0, 1));
        bm0 = fmaxf(bm0, __shfl_xor_sync(0xffffffffu, bm0, 2));
        bm1 = fmaxf(bm1, __shfl_xor_sync(0xffffffffu, bm1, 1));
        bm1 = fmaxf(bm1, __shfl_xor_sync(0xffffffffu, bm1, 2));
        const float mn0 = fmaxf(m0, bm0), mn1 = fmaxf(m1, bm1);
        const float al0 = exp2f(ksc * (m0 - mn0));
        const float al1 = exp2f(ksc * (m1 - mn1));
        l0 *= al0; l1 *= al1;
#pragma unroll
        for (int nt = 0; nt < 16; ++nt) {
            oacc[nt][0] *= al0; oacc[nt][1] *= al0;
            oacc[nt][2] *= al1; oacc[nt][3] *= al1;
        }
        m0 = mn0; m1 = mn1;

        unsigned pa[8][4];
        float s0 = 0.f, s1 = 0.f;
#pragma unroll
        for (int j = 0; j < 8; ++j) {
            const float p00 = exp2f(ksc * (sacc[2*j][0] - mn0));
            const float p01 = exp2f(ksc * (sacc[2*j][1] - mn0));
            const float p02 = exp2f(ksc * (sacc[2*j][2] - mn1));
            const float p03 = exp2f(ksc * (sacc[2*j][3] - mn1));
            const float p10 = exp2f(ksc * (sacc[2*j+1][0] - mn0));
            const float p11 = exp2f(ksc * (sacc[2*j+1][1] - mn0));
            const float p12 = exp2f(ksc * (sacc[2*j+1][2] - mn1));
            const float p13 = exp2f(ksc * (sacc[2*j+1][3] - mn1));
            s0 += p00 + p01 + p10 + p11;
            s1 += p02 + p03 + p12 + p13;
            pa[j][0] = ph2(p00, p01);
            pa[j][1] = ph2(p02, p03);
            pa[j][2] = ph2(p10, p11);
            pa[j][3] = ph2(p12, p13);
        }
        s0 += __shfl_xor_sync(0xffffffffu, s0, 1);
        s0 += __shfl_xor_sync(0xffffffffu, s0, 2);
        s1 += __shfl_xor_sync(0xffffffffu, s1, 1);
        s1 += __shfl_xor_sync(0xffffffffu, s1, 2);
        l0 += s0; l1 += s1;

#pragma unroll
        for (int j = 0; j < 8; ++j) {
#pragma unroll
            for (int nt2 = 0; nt2 < 8; ++nt2) {
                const int r = nt2 * 16 + b_r;
                unsigned bv[4];
                ldsm_x4(bv, Vst + r * 256 + (((j * 2 + b_c) ^ (r & 7)) << 4));
                mma_f16(oacc[2 * nt2],     pa[j], bv[0], bv[1]);
                mma_f16(oacc[2 * nt2 + 1], pa[j], bv[2], bv[3]);
            }
        }
        __syncthreads();
        if (kb + 2 < 8) {
            const long koff = (long)(kb + 2) * 128;
#pragma unroll
            for (int i = 0; i < 8; ++i) {
                const int c = vcbase + i;
                cp_async16(Vst + srow * 256 + ((c ^ rx) << 4), Vsrc + koff + c * 8);
            }
            CP_COMMIT();
        }
    }

    const float i0 = 1.f / l0, i1 = 1.f / l1;
    const int r0 = qb + w * 16 + g;
    __half* orow0 = Og + (long)r0 * EV + h * 128;
    __half* orow1 = orow0 + (long)8 * EV;
#pragma unroll
    for (int nt = 0; nt < 16; ++nt) {
        *(__half2*)(orow0 + nt * 8 + tq * 2) =
            __floats2half2_rn(oacc[nt][0] * i0, oacc[nt][1] * i0);
        *(__half2*)(orow1 + nt * 8 + tq * 2) =
            __floats2half2_rn(oacc[nt][2] * i1, oacc[nt][3] * i1);
    }
}

// ---- simple per-tensor fp32 -> fp16 conversion (DRAM-bound, ~10 instr) ----
__global__ void cvt_h(const float4* __restrict__ in, __half2* __restrict__ out, int n4)
{
    int i = blockIdx.x * blockDim.x + threadIdx.x;
    if (i >= n4) return;
    float4 v = in[i];
    out[2 * i]     = __floats2half2_rn(v.x, v.y);
    out[2 * i + 1] = __floats2half2_rn(v.z, v.w);
}

// ---- fused split-K reduce for qlat (8 planes) and kvlat (8 planes) ----
#define QN4  (S_LEN * QLORA / 4)    // 393216
#define KVN4 (S_LEN * KVLORA / 4)   // 131072
__global__ void reduce_lat(const float* __restrict__ qlp, const float* __restrict__ kvlp,
                           __half* __restrict__ qlath, __half* __restrict__ kvlath)
{
    int i = blockIdx.x * blockDim.x + threadIdx.x;
    const float* in;
    __half* out;
    long idx, stride;
    if (i < QN4)             { in = qlp;  out = qlath;  idx = i;        stride = QN4;  }
    else if (i < QN4 + KVN4) { in = kvlp; out = kvlath; idx = i - QN4;  stride = KVN4; }
    else return;
    float4 s = ((const float4*)in)[idx];
#pragma unroll
    for (int p = 1; p < 8; ++p) {
        float4 v = ((const float4*)in)[idx + (long)p * stride];
        s.x += v.x; s.y += v.y; s.z += v.z; s.w += v.w;
    }
    __half2* d = (__half2*)out + idx * 2;
    d[0] = __floats2half2_rn(s.x, s.y);
    d[1] = __floats2half2_rn(s.z, s.w);
}

// ---- RoPE cos/sin table: 1024 positions x 32 freqs (one tiny launch) ----
__global__ void rope_tab(float2* __restrict__ tab)
{
    int idx = blockIdx.x * blockDim.x + threadIdx.x;
    if (idx >= S_LEN * 32) return;
    int s = idx >> 5, i = idx & 31;
    int m = (2 * i) & 31;
    float invf = exp2f(-(float)m * (13.287712379549449f / 32.0f));  // 10000^(-m/32)
    float ang = (float)s * invf;
    float sn, cs;
    sincosf(ang, &sn, &cs);
    tab[idx] = make_float2(cs, sn);
}

// Fused interleaved RoPE over dims [128,192) for BOTH q and k, table-driven.
__global__ void rope_qk(__half* __restrict__ Q, __half* __restrict__ K,
                        const float2* __restrict__ tab)
{
    long idx = (long)blockIdx.x * blockDim.x + threadIdx.x;
    if (idx >= (long)2 * S_LEN * NHEADS * 32) return;
    __half* X = (idx >> 22) ? K : Q;
    long id = idx & 0x3FFFFF;
    int i = (int)(id & 31);
    int h = (int)((id >> 5) & (NHEADS - 1));
    int s = (int)(id >> 12);

    float2 t = tab[s * 32 + i];
    __half2* p = (__half2*)(X + ((long)s * NHEADS + h) * DQd + DNd + 2 * i);
    float2 v = __half22float2(*p);
    *p = __floats2half2_rn(v.x * t.x - v.y * t.y, v.x * t.y + v.y * t.x);
}

extern "C" void kernel_launch(void* const* d_in, const int* in_sizes, int n_in,
                              void* d_out, int out_size)
{
    const float* X    = (const float*)d_in[0];
    const float* Wqa  = (const float*)d_in[1];
    const float* Wkva = (const float*)d_in[2];
    const float* Wqb  = (const float*)d_in[3];
    const float* Wkb  = (const float*)d_in[4];
    const float* Wvb  = (const float*)d_in[5];
    const float* Wo   = (const float*)d_in[6];
    float* out = (float*)d_out;

    __half *xh, *wqah, *wkvah, *wqbh, *wkbh, *wvbh, *woh;
    __half *qlath, *kvlath, *qh, *kh, *vth, *aoh;
    float *qlp, *kvlp;
    float2* rtab;
    cudaGetSymbolAddress((void**)&xh, g_xh);
    cudaGetSymbolAddress((void**)&wqah, g_wqah);
    cudaGetSymbolAddress((void**)&wkvah, g_wkvah);
    cudaGetSymbolAddress((void**)&wqbh, g_wqbh);
    cudaGetSymbolAddress((void**)&wkbh, g_wkbh);
    cudaGetSymbolAddress((void**)&wvbh, g_wvbh);
    cudaGetSymbolAddress((void**)&woh, g_woh);
    cudaGetSymbolAddress((void**)&qlp, g_qlp);
    cudaGetSymbolAddress((void**)&kvlp, g_kvlp);
    cudaGetSymbolAddress((void**)&qlath, g_qlath);
    cudaGetSymbolAddress((void**)&kvlath, g_kvlath);
    cudaGetSymbolAddress((void**)&qh, g_qh);
    cudaGetSymbolAddress((void**)&kh, g_kh);
    cudaGetSymbolAddress((void**)&vth, g_vth);
    cudaGetSymbolAddress((void**)&aoh, g_aoh);
    cudaGetSymbolAddress((void**)&rtab, g_rtab);

    const int SMEM = 3 * STG_B;  // 98304
    cudaFuncSetAttribute((const void*)hgemm_nt<0, false, true>,
                         cudaFuncAttributeMaxDynamicSharedMemorySize, SMEM);
    cudaFuncSetAttribute((const void*)hgemm_nt<0, true, false>,
                         cudaFuncAttributeMaxDynamicSharedMemorySize, SMEM);
    cudaFuncSetAttribute((const void*)hgemm_nt<1, false, false>,
                         cudaFuncAttributeMaxDynamicSharedMemorySize, SMEM);
    cudaFuncSetAttribute((const void*)hgemm_nt<1, true, false>,
                         cudaFuncAttributeMaxDynamicSharedMemorySize, SMEM);
    cudaFuncSetAttribute((const void*)flash_attn,
                         cudaFuncAttributeMaxDynamicSharedMemorySize, FA_SMEM);

    const dim3 blk(256);

    // launches 0-6: simple fp32->fp16 conversions (DRAM-bound)
    {
        struct { const float* s; __half* d; long n4; } cv[7] = {
            {X,    xh,    (long)S_LEN * DMODEL / 4},
            {Wqa,  wqah,  (long)QLORA * DMODEL / 4},
            {Wkva, wkvah, (long)KVLORA * DMODEL / 4},
            {Wqb,  wqbh,  (long)EQ * QLORA / 4},
            {Wkb,  wkbh,  (long)EQ * KVLORA / 4},
            {Wvb,  wvbh,  (long)EV * KVLORA / 4},
            {Wo,   woh,   (long)DMODEL * EV / 4},
        };
        for (int j = 0; j < 7; ++j) {
            int n4 = (int)cv[j].n4;
            cvt_h<<<(n4 + 255) / 256, 256>>>((const float4*)cv[j].s, (__half2*)cv[j].d, n4);
        }
    }

    // launch 7: FUSED qlat + kvlat partials (split-K 8 x 896 each)
    hgemm_nt<0, false, true><<<dim3(16, S_LEN / 128, 8), blk, SMEM>>>(
        xh, wqah, qlp, DMODEL, DMODEL, DMODEL, QLORA, 0, 0, (long)S_LEN * QLORA, 896,
        wkvah, kvlp, KVLORA, (long)S_LEN * KVLORA, 12);
    // launch 8: fused reduce (qlat + kvlat)
    reduce_lat<<<(QN4 + KVN4) / 256, 256>>>(qlp, kvlp, qlath, kvlath);

    // launch 9: k = kvlath @ Wkb^T  [1024, 24576]
    hgemm_nt<1, false, false><<<dim3(EQ / 128, S_LEN / 128, 1), blk, SMEM>>>(
        kvlath, wkbh, kh, KVLORA, KVLORA, KVLORA, EQ, 0, 0, 0, 0,
        nullptr, nullptr, 0, 0, 0);
    // launch 10: vt = Wvbh @ kvlath^T  [16384, 1024]
    hgemm_nt<1, false, false><<<dim3(S_LEN / 128, EV / 128, 1), blk, SMEM>>>(
        wvbh, kvlath, vth, KVLORA, KVLORA, KVLORA, S_LEN, 0, 0, 0, 0,
        nullptr, nullptr, 0, 0, 0);
    // launch 11: q = qlath @ Wqb^T  [1024, 24576]  (SWAP)
    hgemm_nt<1, true, false><<<dim3(S_LEN / 128, EQ / 128, 1), blk, SMEM>>>(
        qlath, wqbh, qh, QLORA, QLORA, QLORA, EQ, 0, 0, 0, 0,
        nullptr, nullptr, 0, 0, 0);

    // launch 12: RoPE table; launch 13: table-driven RoPE on q and k
    rope_tab<<<(S_LEN * 32) / 256, 256>>>(rtab);
    rope_qk<<<(2 * S_LEN * NHEADS * 32) / 256, 256>>>(qh, kh, rtab);

    // launch 14: fused flash attention -> aoh fp16
    flash_attn<<<dim3(S_LEN / 128, NHEADS), blk, FA_SMEM>>>(qh, kh, vth, aoh);

    // launch 15: out = attn_out @ Wo^T  [1024, 7168] fp32  (SWAP)
    hgemm_nt<0, true, false><<<dim3(S_LEN / 128, DMODEL / 128, 1), blk, SMEM>>>(
        aoh, woh, out, EV, EV, EV, DMODEL, 0, 0, 0, 0,
        nullptr, nullptr, 0, 0, 0);
}